// round 1
// baseline (speedup 1.0000x reference)
#include <cuda_runtime.h>
#include <cstdint>
#include <cstddef>

#define NEGV -1e30f

constexpr int Bb = 32, Tt = 256, S = 258, E = 128, Q = 20, G = 80, Kk = 50, Ll = 8;
constexpr int ROWS = S * Bb;       // 8256  (row = s*32 + b, s-major)
constexpr int ROWS_PAD = 8320;     // padded to 65*128

// Scratch (device globals; no allocation allowed)
__device__ float g_pre_f[ROWS_PAD * G];   // input gates, forward dir
__device__ float g_pre_b[ROWS_PAD * G];   // input gates, backward dir
__device__ float g_hf[S * Bb * Q];        // forward hidden states
__device__ float g_hb[S * Bb * Q];        // backward hidden states

__device__ __forceinline__ float tanhf_fast(float x) {
    return __fdividef(2.f, 1.f + __expf(-2.f * x)) - 1.f;
}

// ---------------------------------------------------------------------------
// Kernel 1: embedding gather + X @ [W_ih_f | W_ih_b]  ->  pre-gates
// C[8256,160] = A[8256,128] * W[128,160], A rows gathered from emb via tokens.
// Tiled GEMM: 128 rows x 160 cols per block, k in 4 chunks of 32.
// ---------------------------------------------------------------------------
__global__ __launch_bounds__(256) void k1_embed_gemm(
    const int* __restrict__ x, const float* __restrict__ emb,
    const float* __restrict__ Wf, const float* __restrict__ bfv,
    const float* __restrict__ Wb, const float* __restrict__ bbv)
{
    __shared__ int tok[128];
    __shared__ float As[32][132];   // [k][row], padded stride
    __shared__ float Ws[32][164];   // [k][col], padded stride
    const int tid = threadIdx.x;
    const int row0 = blockIdx.x * 128;

    if (tid < 128) {
        int r = row0 + tid;
        int tk = 0;
        if (r < ROWS) {
            int s = r >> 5, b = r & 31;
            tk = (s == 0) ? 2 : ((s == S - 1) ? 3 : x[b * Tt + (s - 1)]);
        }
        tok[tid] = tk;
    }
    __syncthreads();

    float acc[8][10];
#pragma unroll
    for (int i = 0; i < 8; i++)
#pragma unroll
        for (int j = 0; j < 10; j++) acc[i][j] = 0.f;

    const int ry = (tid >> 4) << 3;     // 8-row group
    const int cx = (tid & 15) * 10;     // 10-col group

    for (int kc = 0; kc < 4; kc++) {
        // load A tile (transposed into shared): 128 rows x 32 k
#pragma unroll
        for (int i = 0; i < 4; i++) {
            int f = tid + i * 256;          // float4 id
            int r = f >> 3, k4 = f & 7;
            const float4 v = *(const float4*)&emb[(size_t)tok[r] * 128 + kc * 32 + k4 * 4];
            As[k4 * 4 + 0][r] = v.x; As[k4 * 4 + 1][r] = v.y;
            As[k4 * 4 + 2][r] = v.z; As[k4 * 4 + 3][r] = v.w;
        }
        // load W tile: 32 k x 160 cols (cols 0..79 fwd, 80..159 bwd)
#pragma unroll
        for (int i = 0; i < 5; i++) {
            int f = tid + i * 256;          // float4 id, 1280 total
            int kk = f / 40, c = (f % 40) * 4;
            const float* src = (c < 80) ? (Wf + (size_t)(kc * 32 + kk) * 80 + c)
                                        : (Wb + (size_t)(kc * 32 + kk) * 80 + (c - 80));
            *(float4*)&Ws[kk][c] = *(const float4*)src;
        }
        __syncthreads();

#pragma unroll
        for (int kk = 0; kk < 32; kk++) {
            float4 a0 = *(const float4*)&As[kk][ry];
            float4 a1 = *(const float4*)&As[kk][ry + 4];
            float av[8] = {a0.x, a0.y, a0.z, a0.w, a1.x, a1.y, a1.z, a1.w};
            float bv[10];
#pragma unroll
            for (int j = 0; j < 10; j += 2) {
                float2 w2 = *(const float2*)&Ws[kk][cx + j];
                bv[j] = w2.x; bv[j + 1] = w2.y;
            }
#pragma unroll
            for (int i = 0; i < 8; i++)
#pragma unroll
                for (int j = 0; j < 10; j++)
                    acc[i][j] = fmaf(av[i], bv[j], acc[i][j]);
        }
        __syncthreads();
    }

    // add bias, store (cols never straddle the 80 boundary since cx is a mult of 10)
    const bool isF = (cx < 80);
    const int c0 = isF ? cx : cx - 80;
    const float* bsrc = isF ? bfv : bbv;
    float bias[10];
#pragma unroll
    for (int j = 0; j < 10; j++) bias[j] = bsrc[c0 + j];
    float* base = isF ? g_pre_f : g_pre_b;
#pragma unroll
    for (int i = 0; i < 8; i++) {
        int r = row0 + ry + i;              // < 8320 always (padded arrays)
        float* dst = base + (size_t)r * 80 + c0;
#pragma unroll
        for (int j = 0; j < 10; j += 2) {
            float2 v;
            v.x = acc[i][j] + bias[j];
            v.y = acc[i][j + 1] + bias[j + 1];
            *(float2*)&dst[j] = v;
        }
    }
}

// ---------------------------------------------------------------------------
// Kernel 2: LSTM recurrence. One block per (direction, batch): 64 blocks x 80 thr.
// Thread g computes gate column g; W_hh column in registers; h in shared.
// Two-phase step: (gates+activation) -> sync -> (cell update by threads g<20).
// Pre-gates prefetched one step ahead to hide L2 latency.
// ---------------------------------------------------------------------------
__global__ __launch_bounds__(80) void k2_lstm(
    const float* __restrict__ Whf, const float* __restrict__ Whb)
{
    const int dir = blockIdx.x >> 5;
    const int b = blockIdx.x & 31;
    const int g = threadIdx.x;              // 0..79
    const float* pre = dir ? g_pre_b : g_pre_f;
    const float* Wh  = dir ? Whb : Whf;
    float* hout      = dir ? g_hb : g_hf;

    float w[20];
#pragma unroll
    for (int j = 0; j < 20; j++) w[j] = Wh[j * 80 + g];

    __shared__ __align__(16) float h_sh[20];
    __shared__ __align__(16) float gact[20][4];   // [cell q][i,f,g,o] activated
    if (g < 20) h_sh[g] = 0.f;
    float c = 0.f;
    const int q = g % 20;
    const int gt = g / 20;                  // 0=i 1=f 2=g 3=o  (torch order)
    __syncthreads();

    const int sstep = dir ? -1 : 1;
    int s = dir ? (S - 1) : 0;
    float p = __ldg(&pre[((size_t)s * 32 + b) * 80 + g]);

    for (int it = 0; it < S; it++) {
        const float pc = p;
        int sn = s + sstep;
        int snc = sn < 0 ? 0 : (sn > S - 1 ? S - 1 : sn);
        p = __ldg(&pre[((size_t)snc * 32 + b) * 80 + g]);   // prefetch next step

        float hv[20];
        {
            const float4* h4 = (const float4*)h_sh;
            float4 t0 = h4[0], t1 = h4[1], t2 = h4[2], t3 = h4[3], t4 = h4[4];
            hv[0]=t0.x; hv[1]=t0.y; hv[2]=t0.z; hv[3]=t0.w;
            hv[4]=t1.x; hv[5]=t1.y; hv[6]=t1.z; hv[7]=t1.w;
            hv[8]=t2.x; hv[9]=t2.y; hv[10]=t2.z; hv[11]=t2.w;
            hv[12]=t3.x; hv[13]=t3.y; hv[14]=t3.z; hv[15]=t3.w;
            hv[16]=t4.x; hv[17]=t4.y; hv[18]=t4.z; hv[19]=t4.w;
        }
        float a0 = pc, a1 = 0.f, a2 = 0.f, a3 = 0.f;
#pragma unroll
        for (int j = 0; j < 20; j += 4) {
            a0 = fmaf(hv[j],     w[j],     a0);
            a1 = fmaf(hv[j + 1], w[j + 1], a1);
            a2 = fmaf(hv[j + 2], w[j + 2], a2);
            a3 = fmaf(hv[j + 3], w[j + 3], a3);
        }
        float z = (a0 + a1) + (a2 + a3);
        // gate g (gt==2) uses tanh, others sigmoid; branch-free via shared exp
        float zz = (gt == 2) ? 2.f * z : z;
        float r = __fdividef(1.f, 1.f + __expf(-zz));
        float act = (gt == 2) ? (2.f * r - 1.f) : r;
        gact[q][gt] = act;
        __syncthreads();

        if (g < 20) {
            float4 ga = *(const float4*)gact[g];    // i,f,g,o
            c = fmaf(ga.y, c, ga.x * ga.z);         // c = f*c + i*tanh(g)
            float h = ga.w * tanhf_fast(c);         // h = o*tanh(c)
            h_sh[g] = h;
            hout[((size_t)s * 32 + b) * 20 + g] = h;
        }
        __syncthreads();
        s = sn;
    }
}

// ---------------------------------------------------------------------------
// Kernel 3: emission. Only the L=8 needed diagonals of the score tensor.
// Block per t (256 blocks), thread per (l,b) pair (256 threads).
// cat(b, s0, t) = [hf[t+2]-hf[s0+1] ; hb[s0]-hb[t+1]], then 40->20(tanh)->50 MLP.
// ---------------------------------------------------------------------------
__global__ __launch_bounds__(256) void k3_emis(
    const float* __restrict__ W1, const float* __restrict__ b1,
    const float* __restrict__ W2, const float* __restrict__ b2,
    float* __restrict__ out)
{
    __shared__ float W1s[40 * 20];
    __shared__ float b1s[20];
    __shared__ float W2s[20 * 52];   // rows padded to 52 for float4
    __shared__ float b2s[52];
    const int tid = threadIdx.x;
    const int t = blockIdx.x;

    for (int i = tid; i < 800; i += 256) W1s[i] = W1[i];
    if (tid < 20) b1s[tid] = b1[tid];
    for (int i = tid; i < 20 * 52; i += 256) {
        int qq = i / 52, k = i % 52;
        W2s[i] = (k < 50) ? W2[qq * 50 + k] : 0.f;
    }
    if (tid < 52) b2s[tid] = (tid < 50) ? b2[tid] : 0.f;
    __syncthreads();

    const int l = tid >> 5, b = tid & 31;   // warp-uniform validity (l,t fixed per warp)
    const int s0 = t - 7 + l;
    float* op = out + ((((size_t)l * 256 + t) * 32 + b) * 50);

    if (s0 < 0) {
#pragma unroll
        for (int k = 0; k < 50; k += 2) *(float2*)&op[k] = make_float2(NEGV, NEGV);
        return;
    }

    float cat[40];
    const float* hfe = g_hf + ((size_t)(t + 2) * 32 + b) * 20;
    const float* hfs = g_hf + ((size_t)(s0 + 1) * 32 + b) * 20;
    const float* hbs = g_hb + ((size_t)s0 * 32 + b) * 20;
    const float* hbe = g_hb + ((size_t)(t + 1) * 32 + b) * 20;
#pragma unroll
    for (int j = 0; j < 20; j += 4) {
        float4 a  = *(const float4*)(hfe + j), c4 = *(const float4*)(hfs + j);
        cat[j]     = a.x - c4.x; cat[j + 1] = a.y - c4.y;
        cat[j + 2] = a.z - c4.z; cat[j + 3] = a.w - c4.w;
        float4 d  = *(const float4*)(hbs + j), e4 = *(const float4*)(hbe + j);
        cat[20 + j]     = d.x - e4.x; cat[20 + j + 1] = d.y - e4.y;
        cat[20 + j + 2] = d.z - e4.z; cat[20 + j + 3] = d.w - e4.w;
    }

    float hid[20];
#pragma unroll
    for (int v = 0; v < 20; v++) hid[v] = b1s[v];
#pragma unroll
    for (int j = 0; j < 40; j++) {
        float cj = cat[j];
#pragma unroll
        for (int v = 0; v < 20; v += 4) {
            float4 wv = *(const float4*)&W1s[j * 20 + v];
            hid[v]     = fmaf(cj, wv.x, hid[v]);
            hid[v + 1] = fmaf(cj, wv.y, hid[v + 1]);
            hid[v + 2] = fmaf(cj, wv.z, hid[v + 2]);
            hid[v + 3] = fmaf(cj, wv.w, hid[v + 3]);
        }
    }
#pragma unroll
    for (int v = 0; v < 20; v++) hid[v] = tanhf_fast(hid[v]);

    float o[52];
#pragma unroll
    for (int v = 0; v < 52; v++) o[v] = b2s[v];
#pragma unroll
    for (int qq = 0; qq < 20; qq++) {
        float hq = hid[qq];
#pragma unroll
        for (int v = 0; v < 52; v += 4) {
            float4 wv = *(const float4*)&W2s[qq * 52 + v];
            o[v]     = fmaf(hq, wv.x, o[v]);
            o[v + 1] = fmaf(hq, wv.y, o[v + 1]);
            o[v + 2] = fmaf(hq, wv.z, o[v + 2]);
            o[v + 3] = fmaf(hq, wv.w, o[v + 3]);
        }
    }
#pragma unroll
    for (int k = 0; k < 50; k += 2) *(float2*)&op[k] = make_float2(o[k], o[k + 1]);
}

// ---------------------------------------------------------------------------
extern "C" void kernel_launch(void* const* d_in, const int* in_sizes, int n_in,
                              void* d_out, int out_size)
{
    const int*   x   = (const int*)d_in[0];
    const float* emb = (const float*)d_in[1];
    const float* Wif = (const float*)d_in[2];
    const float* Whf = (const float*)d_in[3];
    const float* bf  = (const float*)d_in[4];
    const float* Wib = (const float*)d_in[5];
    const float* Whb = (const float*)d_in[6];
    const float* bb  = (const float*)d_in[7];
    const float* W1  = (const float*)d_in[8];
    const float* b1  = (const float*)d_in[9];
    const float* W2  = (const float*)d_in[10];
    const float* b2  = (const float*)d_in[11];
    float* out = (float*)d_out;

    k1_embed_gemm<<<(ROWS + 127) / 128, 256>>>(x, emb, Wif, bf, Wib, bb);
    k2_lstm<<<64, 80>>>(Whf, Whb);
    k3_emis<<<256, 256>>>(W1, b1, W2, b2, out);
}

// round 2
// speedup vs baseline: 1.2160x; 1.2160x over previous
#include <cuda_runtime.h>
#include <cstdint>
#include <cstddef>

#define NEGV -1e30f

constexpr int Bb = 32, Tt = 256, S = 258, E = 128, Q = 20, G = 80, Kk = 50, Ll = 8;
constexpr int ROWS = S * Bb;       // 8256  (row = s*32 + b, s-major)
constexpr int ROWS_PAD = 8320;

// Scratch (device globals; no allocation allowed)
// pre layout: [row][cell q][gate i,f,g,o]  (permuted from standard gt*20+q)
__device__ float g_pre_f[ROWS_PAD * G];
__device__ float g_pre_b[ROWS_PAD * G];
__device__ float g_hf[S * Bb * Q];
__device__ float g_hb[S * Bb * Q];

// ---- packed f32x2 + MUFU tanh helpers -------------------------------------
__device__ __forceinline__ unsigned long long pk2(float lo, float hi) {
    unsigned long long r;
    asm("mov.b64 %0, {%1, %2};" : "=l"(r) : "f"(lo), "f"(hi));
    return r;
}
__device__ __forceinline__ void upk2(float& lo, float& hi, unsigned long long v) {
    asm("mov.b64 {%0, %1}, %2;" : "=f"(lo), "=f"(hi) : "l"(v));
}
__device__ __forceinline__ void ffma2(unsigned long long& d, unsigned long long a,
                                      unsigned long long b) {
    asm("fma.rn.f32x2 %0, %1, %2, %0;" : "+l"(d) : "l"(a), "l"(b));
}
__device__ __forceinline__ float tanh_ap(float x) {
    float y;
    asm("tanh.approx.f32 %0, %1;" : "=f"(y) : "f"(x));
    return y;
}

// ---------------------------------------------------------------------------
// Kernel 1: embedding gather + X @ [W_ih_f | W_ih_b]  ->  pre-gates (permuted)
// 129 blocks x 64 rows x 160 cols; FFMA2 inner product; one full SM wave.
// ---------------------------------------------------------------------------
__global__ __launch_bounds__(256) void k1_embed_gemm(
    const int* __restrict__ x, const float* __restrict__ emb,
    const float* __restrict__ Wf, const float* __restrict__ bfv,
    const float* __restrict__ Wb, const float* __restrict__ bbv)
{
    __shared__ int tok[64];
    __shared__ float As[32][68];     // [k][row]
    __shared__ float Ws[32][164];    // [k][permuted col]  col = d*80 + q*4 + gt
    __shared__ float bias_sh[160];
    const int tid = threadIdx.x;
    const int row0 = blockIdx.x * 64;

    if (tid < 64) {
        int r = row0 + tid;
        int s = r >> 5, b = r & 31;
        tok[tid] = (s == 0) ? 2 : ((s == S - 1) ? 3 : x[b * Tt + (s - 1)]);
    }
    for (int i = tid; i < 160; i += 256) {
        int d = i / 80, rr = i % 80, q = rr >> 2, gt = rr & 3;
        bias_sh[i] = (d ? bbv : bfv)[gt * 20 + q];
    }
    __syncthreads();

    unsigned long long acc2[4][5];
#pragma unroll
    for (int i = 0; i < 4; i++)
#pragma unroll
        for (int j = 0; j < 5; j++) acc2[i][j] = 0ull;

    const int ry = (tid >> 4) << 2;      // 4-row group
    const int cx = (tid & 15) * 10;      // 10 permuted cols

    for (int kc = 0; kc < 4; kc++) {
        // A tile: 64 rows x 32 k, transposed into shared
#pragma unroll
        for (int i = 0; i < 2; i++) {
            int f = tid + i * 256;                 // float4 id (512 total)
            int r = f >> 3, k4 = f & 7;
            const float4 v = *(const float4*)&emb[(size_t)tok[r] * 128 + kc * 32 + k4 * 4];
            As[k4 * 4 + 0][r] = v.x; As[k4 * 4 + 1][r] = v.y;
            As[k4 * 4 + 2][r] = v.z; As[k4 * 4 + 3][r] = v.w;
        }
        // W tile, permuted: shared col q*4+gt <- source col gt*20+q
#pragma unroll
        for (int i = 0; i < 5; i++) {
            int f = tid + i * 256;                 // permuted float4 id (1280 total)
            int kk = f / 40, c4 = f % 40;          // c4 = (d*20 + q)
            int d = c4 / 20, q = c4 % 20;
            const float* W = d ? Wb : Wf;
            const float* src = W + (size_t)(kc * 32 + kk) * 80 + q;
            float4 v;
            v.x = src[0]; v.y = src[20]; v.z = src[40]; v.w = src[60];
            *(float4*)&Ws[kk][c4 * 4] = v;
        }
        __syncthreads();

#pragma unroll
        for (int kk = 0; kk < 32; kk++) {
            float4 a = *(const float4*)&As[kk][ry];
            unsigned long long av[4] = {pk2(a.x, a.x), pk2(a.y, a.y),
                                        pk2(a.z, a.z), pk2(a.w, a.w)};
            unsigned long long w2[5];
#pragma unroll
            for (int j = 0; j < 5; j++)
                w2[j] = *(const unsigned long long*)&Ws[kk][cx + 2 * j];
#pragma unroll
            for (int i = 0; i < 4; i++)
#pragma unroll
                for (int j = 0; j < 5; j++) ffma2(acc2[i][j], av[i], w2[j]);
        }
        __syncthreads();
    }

    const int d = (cx >= 80);
    const int c0 = cx - d * 80;
    float* base = d ? g_pre_b : g_pre_f;
#pragma unroll
    for (int i = 0; i < 4; i++) {
        int r = row0 + ry + i;
        float* dst = base + (size_t)r * 80 + c0;
#pragma unroll
        for (int j = 0; j < 5; j++) {
            float lo, hi;
            upk2(lo, hi, acc2[i][j]);
            float2 v;
            v.x = lo + bias_sh[cx + 2 * j];
            v.y = hi + bias_sh[cx + 2 * j + 1];
            *(float2*)&dst[2 * j] = v;
        }
    }
}

// ---------------------------------------------------------------------------
// Kernel 2: LSTM recurrence. One WARP per (direction, batch): 64 blocks x 32.
// Lane q owns cell q: 4 gate dot products as 40 FFMA2 (weights in regs),
// h exchanged via double-buffered shared row, ONE __syncwarp per step,
// activations via MUFU tanh.approx. Pre-gates prefetched one step ahead.
// ---------------------------------------------------------------------------
__global__ __launch_bounds__(32) void k2_lstm(
    const float* __restrict__ Whf, const float* __restrict__ Whb)
{
    const int dir = blockIdx.x >> 5;
    const int b = blockIdx.x & 31;
    const int q = threadIdx.x;
    const float* pre = dir ? g_pre_b : g_pre_f;
    const float* Wh  = dir ? Whb : Whf;
    float* hout      = dir ? g_hb : g_hf;

    unsigned long long wp[4][10];
    if (q < 20) {
#pragma unroll
        for (int gt = 0; gt < 4; gt++)
#pragma unroll
            for (int jp = 0; jp < 10; jp++)
                wp[gt][jp] = pk2(Wh[(2 * jp) * 80 + gt * 20 + q],
                                 Wh[(2 * jp + 1) * 80 + gt * 20 + q]);
    }

    __shared__ __align__(16) float h_sh[2][24];
    if (q < 24) { h_sh[0][q] = 0.f; h_sh[1][q] = 0.f; }
    float c = 0.f;
    __syncwarp();

    const int sst = dir ? -1 : 1;
    int s = dir ? (S - 1) : 0;
    float4 p4 = make_float4(0.f, 0.f, 0.f, 0.f);
    if (q < 20) p4 = *(const float4*)&pre[((size_t)s * 32 + b) * 80 + q * 4];
    int par = 0;

    for (int it = 0; it < S; it++) {
        int sn = s + sst;
        int snc = sn < 0 ? 0 : (sn > S - 1 ? S - 1 : sn);
        if (q < 20) {
            float4 pc = p4;
            p4 = *(const float4*)&pre[((size_t)snc * 32 + b) * 80 + q * 4];

            const unsigned long long* hp = (const unsigned long long*)h_sh[par];
            unsigned long long h2[10];
#pragma unroll
            for (int jp = 0; jp < 10; jp++) h2[jp] = hp[jp];

            unsigned long long a0 = 0ull, a1 = 0ull, a2 = 0ull, a3 = 0ull;
#pragma unroll
            for (int jp = 0; jp < 10; jp++) {
                ffma2(a0, h2[jp], wp[0][jp]);
                ffma2(a1, h2[jp], wp[1][jp]);
                ffma2(a2, h2[jp], wp[2][jp]);
                ffma2(a3, h2[jp], wp[3][jp]);
            }
            float lo, hi;
            upk2(lo, hi, a0); float zi = pc.x + lo + hi;
            upk2(lo, hi, a1); float zf = pc.y + lo + hi;
            upk2(lo, hi, a2); float zg = pc.z + lo + hi;
            upk2(lo, hi, a3); float zo = pc.w + lo + hi;

            float si = fmaf(tanh_ap(0.5f * zi), 0.5f, 0.5f);
            float sf = fmaf(tanh_ap(0.5f * zf), 0.5f, 0.5f);
            float so = fmaf(tanh_ap(0.5f * zo), 0.5f, 0.5f);
            float tg = tanh_ap(zg);
            c = fmaf(sf, c, si * tg);
            float h = so * tanh_ap(c);
            h_sh[par ^ 1][q] = h;
            hout[((size_t)s * 32 + b) * 20 + q] = h;
        }
        __syncwarp();
        par ^= 1;
        s = sn;
    }
}

// ---------------------------------------------------------------------------
// Kernel 3: emission. Only the L=8 needed diagonals.
// Block per t (256), thread per (l,b) (256). K-output split in 2 halves of 26
// to cut register pressure; MUFU tanh.
// ---------------------------------------------------------------------------
__global__ __launch_bounds__(256) void k3_emis(
    const float* __restrict__ W1, const float* __restrict__ b1,
    const float* __restrict__ W2, const float* __restrict__ b2,
    float* __restrict__ out)
{
    __shared__ float W1s[40 * 20];
    __shared__ float b1s[20];
    __shared__ float W2s[20 * 52];   // rows padded to 52
    __shared__ float b2s[52];
    const int tid = threadIdx.x;
    const int t = blockIdx.x;

    for (int i = tid; i < 800; i += 256) W1s[i] = W1[i];
    if (tid < 20) b1s[tid] = b1[tid];
    for (int i = tid; i < 20 * 52; i += 256) {
        int qq = i / 52, k = i % 52;
        W2s[i] = (k < 50) ? W2[qq * 50 + k] : 0.f;
    }
    if (tid < 52) b2s[tid] = (tid < 50) ? b2[tid] : 0.f;
    __syncthreads();

    const int l = tid >> 5, b = tid & 31;
    const int s0 = t - 7 + l;
    float* op = out + ((((size_t)l * 256 + t) * 32 + b) * 50);

    if (s0 < 0) {
#pragma unroll
        for (int k = 0; k < 50; k += 2) *(float2*)&op[k] = make_float2(NEGV, NEGV);
        return;
    }

    float cat[40];
    const float* hfe = g_hf + ((size_t)(t + 2) * 32 + b) * 20;
    const float* hfs = g_hf + ((size_t)(s0 + 1) * 32 + b) * 20;
    const float* hbs = g_hb + ((size_t)s0 * 32 + b) * 20;
    const float* hbe = g_hb + ((size_t)(t + 1) * 32 + b) * 20;
#pragma unroll
    for (int j = 0; j < 20; j += 4) {
        float4 a  = *(const float4*)(hfe + j), c4 = *(const float4*)(hfs + j);
        cat[j]     = a.x - c4.x; cat[j + 1] = a.y - c4.y;
        cat[j + 2] = a.z - c4.z; cat[j + 3] = a.w - c4.w;
        float4 d  = *(const float4*)(hbs + j), e4 = *(const float4*)(hbe + j);
        cat[20 + j]     = d.x - e4.x; cat[20 + j + 1] = d.y - e4.y;
        cat[20 + j + 2] = d.z - e4.z; cat[20 + j + 3] = d.w - e4.w;
    }

    float hid[20];
#pragma unroll
    for (int v = 0; v < 20; v++) hid[v] = b1s[v];
#pragma unroll
    for (int j = 0; j < 40; j++) {
        float cj = cat[j];
#pragma unroll
        for (int v = 0; v < 20; v += 4) {
            float4 wv = *(const float4*)&W1s[j * 20 + v];
            hid[v]     = fmaf(cj, wv.x, hid[v]);
            hid[v + 1] = fmaf(cj, wv.y, hid[v + 1]);
            hid[v + 2] = fmaf(cj, wv.z, hid[v + 2]);
            hid[v + 3] = fmaf(cj, wv.w, hid[v + 3]);
        }
    }
#pragma unroll
    for (int v = 0; v < 20; v++) hid[v] = tanh_ap(hid[v]);

    // output in two halves of 26 cols to limit register pressure
#pragma unroll
    for (int half = 0; half < 2; half++) {
        const int ko = half * 26;
        float o[26];
#pragma unroll
        for (int v = 0; v < 26; v++) o[v] = b2s[ko + v];
#pragma unroll
        for (int qq = 0; qq < 20; qq++) {
            float hq = hid[qq];
            const float* wrow = &W2s[qq * 52 + ko];
#pragma unroll
            for (int v = 0; v < 26; v += 2) {
                float2 wv = *(const float2*)&wrow[v];
                o[v]     = fmaf(hq, wv.x, o[v]);
                o[v + 1] = fmaf(hq, wv.y, o[v + 1]);
            }
        }
        const int lim = (half == 0) ? 26 : 24;   // cols 0..49
#pragma unroll
        for (int k = 0; k < 26; k += 2) {
            if (k < lim) *(float2*)&op[ko + k] = make_float2(o[k], o[k + 1]);
        }
    }
}

// ---------------------------------------------------------------------------
extern "C" void kernel_launch(void* const* d_in, const int* in_sizes, int n_in,
                              void* d_out, int out_size)
{
    const int*   x   = (const int*)d_in[0];
    const float* emb = (const float*)d_in[1];
    const float* Wif = (const float*)d_in[2];
    const float* Whf = (const float*)d_in[3];
    const float* bf  = (const float*)d_in[4];
    const float* Wib = (const float*)d_in[5];
    const float* Whb = (const float*)d_in[6];
    const float* bb  = (const float*)d_in[7];
    const float* W1  = (const float*)d_in[8];
    const float* b1  = (const float*)d_in[9];
    const float* W2  = (const float*)d_in[10];
    const float* b2  = (const float*)d_in[11];
    float* out = (float*)d_out;

    k1_embed_gemm<<<129, 256>>>(x, emb, Wif, bf, Wib, bb);
    k2_lstm<<<64, 32>>>(Whf, Whb);
    k3_emis<<<256, 256>>>(W1, b1, W2, b2, out);
}

// round 3
// speedup vs baseline: 1.3786x; 1.1337x over previous
#include <cuda_runtime.h>
#include <cstdint>
#include <cstddef>

#define NEGV -1e30f

constexpr int Bb = 32, Tt = 256, S = 258, E = 128, Q = 20, G = 80;
constexpr int ROWS = S * Bb;       // 8256 (row = s*32 + b)
constexpr int ROWS_PAD = 8320;

// Scratch. pre layout: [row][cell q * 4 + gate(i,f,g,o)]
__device__ float g_pre_f[ROWS_PAD * G];
__device__ float g_pre_b[ROWS_PAD * G];
__device__ float g_hf[S * Bb * Q];
__device__ float g_hb[S * Bb * Q];

// ---- helpers --------------------------------------------------------------
__device__ __forceinline__ unsigned long long pk2(float lo, float hi) {
    unsigned long long r;
    asm("mov.b64 %0, {%1, %2};" : "=l"(r) : "f"(lo), "f"(hi));
    return r;
}
__device__ __forceinline__ void upk2(float& lo, float& hi, unsigned long long v) {
    asm("mov.b64 {%0, %1}, %2;" : "=f"(lo), "=f"(hi) : "l"(v));
}
__device__ __forceinline__ void ffma2(unsigned long long& d, unsigned long long a,
                                      unsigned long long b) {
    asm("fma.rn.f32x2 %0, %1, %2, %0;" : "+l"(d) : "l"(a), "l"(b));
}
__device__ __forceinline__ void fadd2(unsigned long long& d, unsigned long long a) {
    asm("add.rn.f32x2 %0, %0, %1;" : "+l"(d) : "l"(a));
}
__device__ __forceinline__ float tanh_ap(float x) {
    float y;
    asm("tanh.approx.f32 %0, %1;" : "=f"(y) : "f"(x));
    return y;
}
__device__ __forceinline__ uint32_t s2u(const void* p) {
    uint32_t a;
    asm("{ .reg .u64 t; cvta.to.shared.u64 t, %1; cvt.u32.u64 %0, t; }"
        : "=r"(a) : "l"(p));
    return a;
}
__device__ __forceinline__ void cp_async16(uint32_t dst, const void* src) {
    asm volatile("cp.async.ca.shared.global [%0], [%1], 16;" :: "r"(dst), "l"(src));
}
__device__ __forceinline__ void cp_commit() {
    asm volatile("cp.async.commit_group;" ::: "memory");
}
template <int N> __device__ __forceinline__ void cp_wait() {
    asm volatile("cp.async.wait_group %0;" :: "n"(N) : "memory");
}

// ---------------------------------------------------------------------------
// Kernel 1: embedding gather + X @ [W_ih_f | W_ih_b] -> pre-gates (permuted)
// 129 blocks x 64 rows x 160 cols. cp.async double-buffered k-chunks of 16.
// ---------------------------------------------------------------------------
__global__ __launch_bounds__(256) void k1_embed_gemm(
    const int* __restrict__ x, const float* __restrict__ emb,
    const float* __restrict__ Wf, const float* __restrict__ bfv,
    const float* __restrict__ Wb, const float* __restrict__ bbv)
{
    __shared__ int tok[64];
    __shared__ float bias_sh[160];
    __shared__ float As[2][64][20];    // [buf][row][k(16)+pad4]
    __shared__ float Ws[2][16][164];   // [buf][k][source col 0..159 +pad]
    const int tid = threadIdx.x;
    const int row0 = blockIdx.x * 64;

    if (tid < 64) {
        int r = row0 + tid;
        int s = r >> 5, b = r & 31;
        tok[tid] = (s == 0) ? 2 : ((s == S - 1) ? 3 : x[b * Tt + (s - 1)]);
    }
    for (int i = tid; i < 160; i += 256)
        bias_sh[i] = ((i < 80) ? bfv : bbv)[i % 80];
    __syncthreads();

    // async-load one k-chunk into buffer `bf`
    auto issue = [&](int kc, int bfr) {
        {   // A tile: 64 rows x 16 k = 256 float4, one per thread
            int r = tid >> 2, k4 = tid & 3;
            cp_async16(s2u(&As[bfr][r][k4 * 4]),
                       emb + (size_t)tok[r] * 128 + kc * 16 + k4 * 4);
        }
        // W tile: 16 k x 160 cols = 640 float4
#pragma unroll
        for (int i = 0; i < 3; i++) {
            int f = tid + i * 256;
            if (f < 640) {
                int kk = f / 40, c = (f % 40) * 4;
                const float* src = (c < 80)
                    ? (Wf + (size_t)(kc * 16 + kk) * 80 + c)
                    : (Wb + (size_t)(kc * 16 + kk) * 80 + (c - 80));
                cp_async16(s2u(&Ws[bfr][kk][c]), src);
            }
        }
        cp_commit();
    };

    issue(0, 0);

    unsigned long long acc2[4][5];
#pragma unroll
    for (int i = 0; i < 4; i++)
#pragma unroll
        for (int j = 0; j < 5; j++) acc2[i][j] = 0ull;

    const int ry = (tid >> 4) << 2;     // 4-row group
    const int cx = (tid & 15) * 10;     // 10 source cols

    for (int kc = 0; kc < 8; kc++) {
        const int bfr = kc & 1;
        if (kc < 7) { issue(kc + 1, bfr ^ 1); cp_wait<1>(); }
        else        { cp_wait<0>(); }
        __syncthreads();

#pragma unroll
        for (int kk4 = 0; kk4 < 4; kk4++) {
            float ax[4][4];
#pragma unroll
            for (int r = 0; r < 4; r++) {
                float4 v = *(const float4*)&As[bfr][ry + r][kk4 * 4];
                ax[r][0] = v.x; ax[r][1] = v.y; ax[r][2] = v.z; ax[r][3] = v.w;
            }
#pragma unroll
            for (int t = 0; t < 4; t++) {
                const int kk = kk4 * 4 + t;
                unsigned long long w2[5];
#pragma unroll
                for (int j = 0; j < 5; j++)
                    w2[j] = *(const unsigned long long*)&Ws[bfr][kk][cx + 2 * j];
                unsigned long long av[4] = {
                    pk2(ax[0][t], ax[0][t]), pk2(ax[1][t], ax[1][t]),
                    pk2(ax[2][t], ax[2][t]), pk2(ax[3][t], ax[3][t])};
#pragma unroll
                for (int i = 0; i < 4; i++)
#pragma unroll
                    for (int j = 0; j < 5; j++) ffma2(acc2[i][j], av[i], w2[j]);
            }
        }
        __syncthreads();
    }

    // permuted store: source col c -> slot (c%20)*4 + c/20  (within its dir)
    const int d = (cx >= 80);
    const int c0 = cx - 80 * d;
    const int gt = c0 / 20, q0 = c0 % 20;
    float* base = d ? g_pre_b : g_pre_f;
#pragma unroll
    for (int i = 0; i < 4; i++) {
        int r = row0 + ry + i;
        float* dst = base + (size_t)r * 80 + gt;
#pragma unroll
        for (int j = 0; j < 5; j++) {
            float lo, hi;
            upk2(lo, hi, acc2[i][j]);
            dst[(q0 + 2 * j) * 4]     = lo + bias_sh[cx + 2 * j];
            dst[(q0 + 2 * j + 1) * 4] = hi + bias_sh[cx + 2 * j + 1];
        }
    }
}

// ---------------------------------------------------------------------------
// Kernel 2: LSTM recurrence. One WARP per (dir, batch): 64 blocks x 32.
// Lane q owns cell q. Gates paired (i,f)/(g,o) as f32x2; 4-way split chains;
// h kept duplicated in shared (double-buffered); pre-gates prefetched 4 steps
// ahead through a register pipeline (static index via 4x unroll).
// ---------------------------------------------------------------------------
__global__ __launch_bounds__(32) void k2_lstm(
    const float* __restrict__ Whf, const float* __restrict__ Whb)
{
    const int dir = blockIdx.x >> 5;
    const int b = blockIdx.x & 31;
    const int q = threadIdx.x;
    const int qc = q < 20 ? q : 19;               // clamp for safe loads
    const float* pre = dir ? g_pre_b : g_pre_f;
    const float* Wh  = dir ? Whb : Whf;
    float* hout      = dir ? g_hb : g_hf;

    unsigned long long wif[20], wgo[20];
#pragma unroll
    for (int j = 0; j < 20; j++) {
        wif[j] = pk2(Wh[j * 80 + qc],      Wh[j * 80 + 20 + qc]);
        wgo[j] = pk2(Wh[j * 80 + 40 + qc], Wh[j * 80 + 60 + qc]);
    }

    __shared__ __align__(16) float hdup[2][64];   // (h_j,h_j) pairs
    for (int i = q; i < 128; i += 32) ((float*)hdup)[i] = 0.f;
    float c = 0.f;

    const float* pbase = pre + (size_t)b * 80 + qc * 4;
    float4 buf[4];
#pragma unroll
    for (int k = 0; k < 4; k++) {
        int s = dir ? (S - 1 - k) : k;
        buf[k] = *(const float4*)(pbase + (size_t)s * (32 * 80));
    }
    __syncwarp();

    int par = 0;
    for (int it0 = 0; it0 < 260; it0 += 4) {
#pragma unroll
        for (int u = 0; u < 4; u++) {
            const int it = it0 + u;
            const float4 pc = buf[u];
            {   // refill pipeline slot with step it+4 (clamped)
                int itn = it + 4; itn = itn > S - 1 ? S - 1 : itn;
                int sn = dir ? (S - 1 - itn) : itn;
                buf[u] = *(const float4*)(pbase + (size_t)sn * (32 * 80));
            }

            ulonglong2 hv[10];
            const ulonglong2* hp = (const ulonglong2*)hdup[par];
#pragma unroll
            for (int jj = 0; jj < 10; jj++) hv[jj] = hp[jj];

            unsigned long long aif[4], ago[4];
            aif[0] = pk2(pc.x, pc.y); ago[0] = pk2(pc.z, pc.w);
            aif[1] = aif[2] = aif[3] = 0ull;
            ago[1] = ago[2] = ago[3] = 0ull;
#pragma unroll
            for (int j = 0; j < 20; j++) {
                unsigned long long h2 = (j & 1) ? hv[j >> 1].y : hv[j >> 1].x;
                ffma2(aif[j & 3], h2, wif[j]);
                ffma2(ago[j & 3], h2, wgo[j]);
            }
            fadd2(aif[0], aif[1]); fadd2(aif[2], aif[3]); fadd2(aif[0], aif[2]);
            fadd2(ago[0], ago[1]); fadd2(ago[2], ago[3]); fadd2(ago[0], ago[2]);

            float zi, zf, zg, zo;
            upk2(zi, zf, aif[0]);
            upk2(zg, zo, ago[0]);

            float si = fmaf(tanh_ap(0.5f * zi), 0.5f, 0.5f);
            float sf = fmaf(tanh_ap(0.5f * zf), 0.5f, 0.5f);
            float so = fmaf(tanh_ap(0.5f * zo), 0.5f, 0.5f);
            float tg = tanh_ap(zg);
            c = fmaf(sf, c, si * tg);
            float h = so * tanh_ap(c);

            if (it < S) {
                *(float2*)&hdup[par ^ 1][2 * q] = make_float2(h, h);
                if (q < 20) {
                    int s = dir ? (S - 1 - it) : it;
                    hout[((size_t)s * 32 + b) * 20 + q] = h;
                }
            }
            __syncwarp();
            par ^= 1;
        }
    }
}

// ---------------------------------------------------------------------------
// Kernel 3: emission, only the L=8 needed diagonals.
// ---------------------------------------------------------------------------
__global__ __launch_bounds__(256) void k3_emis(
    const float* __restrict__ W1, const float* __restrict__ b1,
    const float* __restrict__ W2, const float* __restrict__ b2,
    float* __restrict__ out)
{
    __shared__ float W1s[40 * 20];
    __shared__ float b1s[20];
    __shared__ float W2s[20 * 52];
    __shared__ float b2s[52];
    const int tid = threadIdx.x;
    const int t = blockIdx.x;

    for (int i = tid; i < 800; i += 256) W1s[i] = W1[i];
    if (tid < 20) b1s[tid] = b1[tid];
    for (int i = tid; i < 20 * 52; i += 256) {
        int qq = i / 52, k = i % 52;
        W2s[i] = (k < 50) ? W2[qq * 50 + k] : 0.f;
    }
    if (tid < 52) b2s[tid] = (tid < 50) ? b2[tid] : 0.f;
    __syncthreads();

    const int l = tid >> 5, b = tid & 31;
    const int s0 = t - 7 + l;
    float* op = out + ((((size_t)l * 256 + t) * 32 + b) * 50);

    if (s0 < 0) {
#pragma unroll
        for (int k = 0; k < 50; k += 2) *(float2*)&op[k] = make_float2(NEGV, NEGV);
        return;
    }

    float cat[40];
    const float* hfe = g_hf + ((size_t)(t + 2) * 32 + b) * 20;
    const float* hfs = g_hf + ((size_t)(s0 + 1) * 32 + b) * 20;
    const float* hbs = g_hb + ((size_t)s0 * 32 + b) * 20;
    const float* hbe = g_hb + ((size_t)(t + 1) * 32 + b) * 20;
#pragma unroll
    for (int j = 0; j < 20; j += 4) {
        float4 a  = *(const float4*)(hfe + j), c4 = *(const float4*)(hfs + j);
        cat[j]     = a.x - c4.x; cat[j + 1] = a.y - c4.y;
        cat[j + 2] = a.z - c4.z; cat[j + 3] = a.w - c4.w;
        float4 d  = *(const float4*)(hbs + j), e4 = *(const float4*)(hbe + j);
        cat[20 + j]     = d.x - e4.x; cat[20 + j + 1] = d.y - e4.y;
        cat[20 + j + 2] = d.z - e4.z; cat[20 + j + 3] = d.w - e4.w;
    }

    float hid[20];
#pragma unroll
    for (int v = 0; v < 20; v++) hid[v] = b1s[v];
#pragma unroll
    for (int j = 0; j < 40; j++) {
        float cj = cat[j];
#pragma unroll
        for (int v = 0; v < 20; v += 4) {
            float4 wv = *(const float4*)&W1s[j * 20 + v];
            hid[v]     = fmaf(cj, wv.x, hid[v]);
            hid[v + 1] = fmaf(cj, wv.y, hid[v + 1]);
            hid[v + 2] = fmaf(cj, wv.z, hid[v + 2]);
            hid[v + 3] = fmaf(cj, wv.w, hid[v + 3]);
        }
    }
#pragma unroll
    for (int v = 0; v < 20; v++) hid[v] = tanh_ap(hid[v]);

#pragma unroll
    for (int half = 0; half < 2; half++) {
        const int ko = half * 26;
        float o[26];
#pragma unroll
        for (int v = 0; v < 26; v++) o[v] = b2s[ko + v];
#pragma unroll
        for (int qq = 0; qq < 20; qq++) {
            float hq = hid[qq];
            const float* wrow = &W2s[qq * 52 + ko];
#pragma unroll
            for (int v = 0; v < 26; v += 2) {
                float2 wv = *(const float2*)&wrow[v];
                o[v]     = fmaf(hq, wv.x, o[v]);
                o[v + 1] = fmaf(hq, wv.y, o[v + 1]);
            }
        }
        const int lim = (half == 0) ? 26 : 24;
#pragma unroll
        for (int k = 0; k < 26; k += 2) {
            if (k < lim) *(float2*)&op[ko + k] = make_float2(o[k], o[k + 1]);
        }
    }
}

// ---------------------------------------------------------------------------
extern "C" void kernel_launch(void* const* d_in, const int* in_sizes, int n_in,
                              void* d_out, int out_size)
{
    const int*   x   = (const int*)d_in[0];
    const float* emb = (const float*)d_in[1];
    const float* Wif = (const float*)d_in[2];
    const float* Whf = (const float*)d_in[3];
    const float* bf  = (const float*)d_in[4];
    const float* Wib = (const float*)d_in[5];
    const float* Whb = (const float*)d_in[6];
    const float* bb  = (const float*)d_in[7];
    const float* W1  = (const float*)d_in[8];
    const float* b1  = (const float*)d_in[9];
    const float* W2  = (const float*)d_in[10];
    const float* b2  = (const float*)d_in[11];
    float* out = (float*)d_out;

    k1_embed_gemm<<<129, 256>>>(x, emb, Wif, bf, Wib, bb);
    k2_lstm<<<64, 32>>>(Whf, Whb);
    k3_emis<<<256, 256>>>(W1, b1, W2, b2, out);
}

// round 4
// speedup vs baseline: 1.4303x; 1.0375x over previous
#include <cuda_runtime.h>
#include <cstdint>
#include <cstddef>

#define NEGV -1e30f

constexpr int Bb = 32, Tt = 256, S = 258, E = 128, Q = 20, G = 80;
constexpr int ROWS = S * Bb;
constexpr int ROWS_PAD = 8320;

// Scratch. pre layout: [row][cell q * 4 + gate(i,f,g,o)]
__device__ float g_pre_f[ROWS_PAD * G];
__device__ float g_pre_b[ROWS_PAD * G];
__device__ float g_hf[S * Bb * Q];
__device__ float g_hb[S * Bb * Q];

// ---- helpers --------------------------------------------------------------
__device__ __forceinline__ unsigned long long pk2(float lo, float hi) {
    unsigned long long r;
    asm("mov.b64 %0, {%1, %2};" : "=l"(r) : "f"(lo), "f"(hi));
    return r;
}
__device__ __forceinline__ void upk2(float& lo, float& hi, unsigned long long v) {
    asm("mov.b64 {%0, %1}, %2;" : "=f"(lo), "=f"(hi) : "l"(v));
}
__device__ __forceinline__ void ffma2(unsigned long long& d, unsigned long long a,
                                      unsigned long long b) {
    asm("fma.rn.f32x2 %0, %1, %2, %0;" : "+l"(d) : "l"(a), "l"(b));
}
__device__ __forceinline__ void fadd2(unsigned long long& d, unsigned long long a) {
    asm("add.rn.f32x2 %0, %0, %1;" : "+l"(d) : "l"(a));
}
__device__ __forceinline__ float tanh_ap(float x) {
    float y;
    asm("tanh.approx.f32 %0, %1;" : "=f"(y) : "f"(x));
    return y;
}
__device__ __forceinline__ uint32_t s2u(const void* p) {
    uint32_t a;
    asm("{ .reg .u64 t; cvta.to.shared.u64 t, %1; cvt.u32.u64 %0, t; }"
        : "=r"(a) : "l"(p));
    return a;
}
__device__ __forceinline__ void cp_async16(uint32_t dst, const void* src) {
    asm volatile("cp.async.ca.shared.global [%0], [%1], 16;" :: "r"(dst), "l"(src));
}
__device__ __forceinline__ void cp_commit() {
    asm volatile("cp.async.commit_group;" ::: "memory");
}
template <int N> __device__ __forceinline__ void cp_wait() {
    asm volatile("cp.async.wait_group %0;" :: "n"(N) : "memory");
}

// ---------------------------------------------------------------------------
// Kernel 1: embedding gather + X @ [W_ih_f | W_ih_b] -> pre-gates (permuted)
// 129 blocks x 512 threads; 64 rows x 160 cols per block; 2 rows x 10 cols
// per thread; cp.async double-buffered k-chunks of 16.
// ---------------------------------------------------------------------------
__global__ __launch_bounds__(512) void k1_embed_gemm(
    const int* __restrict__ x, const float* __restrict__ emb,
    const float* __restrict__ Wf, const float* __restrict__ bfv,
    const float* __restrict__ Wb, const float* __restrict__ bbv)
{
    __shared__ int tok[64];
    __shared__ float bias_sh[160];
    __shared__ float As[2][64][20];    // [buf][row][k(16)+pad4]
    __shared__ float Ws[2][16][164];   // [buf][k][source col 0..159 +pad]
    const int tid = threadIdx.x;
    const int row0 = blockIdx.x * 64;

    if (tid < 64) {
        int r = row0 + tid;
        int s = r >> 5, b = r & 31;
        tok[tid] = (s == 0) ? 2 : ((s == S - 1) ? 3 : x[b * Tt + (s - 1)]);
    }
    if (tid < 160) bias_sh[tid] = ((tid < 80) ? bfv : bbv)[tid % 80];
    __syncthreads();

    auto issue = [&](int kc, int bfr) {
        if (tid < 256) {     // A tile: 64 rows x 16 k = 256 float4
            int r = tid >> 2, k4 = tid & 3;
            cp_async16(s2u(&As[bfr][r][k4 * 4]),
                       emb + (size_t)tok[r] * 128 + kc * 16 + k4 * 4);
        }
#pragma unroll
        for (int i = 0; i < 2; i++) {   // W tile: 640 float4
            int f = tid + i * 512;
            if (f < 640) {
                int kk = f / 40, c = (f % 40) * 4;
                const float* src = (c < 80)
                    ? (Wf + (size_t)(kc * 16 + kk) * 80 + c)
                    : (Wb + (size_t)(kc * 16 + kk) * 80 + (c - 80));
                cp_async16(s2u(&Ws[bfr][kk][c]), src);
            }
        }
        cp_commit();
    };

    issue(0, 0);

    unsigned long long acc2[2][5];
#pragma unroll
    for (int i = 0; i < 2; i++)
#pragma unroll
        for (int j = 0; j < 5; j++) acc2[i][j] = 0ull;

    const int ry = (tid >> 4) << 1;     // 2-row group (0..62)
    const int cx = (tid & 15) * 10;     // 10 source cols

    for (int kc = 0; kc < 8; kc++) {
        const int bfr = kc & 1;
        if (kc < 7) { issue(kc + 1, bfr ^ 1); cp_wait<1>(); }
        else        { cp_wait<0>(); }
        __syncthreads();

#pragma unroll
        for (int kk4 = 0; kk4 < 4; kk4++) {
            float4 va = *(const float4*)&As[bfr][ry][kk4 * 4];
            float4 vb = *(const float4*)&As[bfr][ry + 1][kk4 * 4];
            float a0[4] = {va.x, va.y, va.z, va.w};
            float a1[4] = {vb.x, vb.y, vb.z, vb.w};
#pragma unroll
            for (int t = 0; t < 4; t++) {
                const int kk = kk4 * 4 + t;
                unsigned long long w2[5];
#pragma unroll
                for (int j = 0; j < 5; j++)
                    w2[j] = *(const unsigned long long*)&Ws[bfr][kk][cx + 2 * j];
                unsigned long long p0 = pk2(a0[t], a0[t]);
                unsigned long long p1 = pk2(a1[t], a1[t]);
#pragma unroll
                for (int j = 0; j < 5; j++) {
                    ffma2(acc2[0][j], p0, w2[j]);
                    ffma2(acc2[1][j], p1, w2[j]);
                }
            }
        }
        __syncthreads();
    }

    // permuted store: source col c (= gt*20+q within dir) -> slot q*4+gt
    const int d = (cx >= 80);
    const int c0 = cx - 80 * d;
    const int gt = c0 / 20, q0 = c0 % 20;
    float* base = d ? g_pre_b : g_pre_f;
#pragma unroll
    for (int i = 0; i < 2; i++) {
        int r = row0 + ry + i;
        float* dst = base + (size_t)r * 80 + gt;
#pragma unroll
        for (int j = 0; j < 5; j++) {
            float lo, hi;
            upk2(lo, hi, acc2[i][j]);
            dst[(q0 + 2 * j) * 4]     = lo + bias_sh[cx + 2 * j];
            dst[(q0 + 2 * j + 1) * 4] = hi + bias_sh[cx + 2 * j + 1];
        }
    }
}

// ---------------------------------------------------------------------------
// Kernel 2: LSTM recurrence. One WARP per (dir, batch): 64 blocks x 32.
// Pre-gates stream through a depth-4 cp.async ring in shared memory, so no
// long-latency LDG ever sits on a register scoreboard inside the loop.
// Lane q owns cell q; gates paired (i,f)/(g,o) as f32x2; h duplicated in a
// double-buffered shared row; one __syncwarp per step; MUFU tanh.
// ---------------------------------------------------------------------------
__global__ __launch_bounds__(32) void k2_lstm(
    const float* __restrict__ Whf, const float* __restrict__ Whb)
{
    const int dir = blockIdx.x >> 5;
    const int b = blockIdx.x & 31;
    const int q = threadIdx.x;
    const int qc = q < 20 ? q : 19;
    const float* pre = dir ? g_pre_b : g_pre_f;
    const float* Wh  = dir ? Whb : Whf;
    float* hout      = dir ? g_hb : g_hf;

    unsigned long long wif[20], wgo[20];
#pragma unroll
    for (int j = 0; j < 20; j++) {
        wif[j] = pk2(Wh[j * 80 + qc],      Wh[j * 80 + 20 + qc]);
        wgo[j] = pk2(Wh[j * 80 + 40 + qc], Wh[j * 80 + 60 + qc]);
    }

    __shared__ __align__(16) float slots[4][80];   // cp.async ring
    __shared__ __align__(16) float hdup[2][64];    // (h_j,h_j) pairs
    for (int i = q; i < 128; i += 32) ((float*)hdup)[i] = 0.f;
    float c = 0.f;

    const float* pbase = pre + (size_t)b * 80 + qc * 4;
    auto rowptr = [&](int it) {
        int itc = it > S - 1 ? S - 1 : it;
        int s = dir ? (S - 1 - itc) : itc;
        return pbase + (size_t)s * (32 * 80);
    };

#pragma unroll
    for (int k = 0; k < 4; k++) {
        if (q < 20) cp_async16(s2u(&slots[k][qc * 4]), rowptr(k));
        cp_commit();
    }
    __syncwarp();

    int par = 0;
    for (int it = 0; it < S; ++it) {
        cp_wait<3>();
        const float4 pc = *(const float4*)&slots[it & 3][qc * 4];

        ulonglong2 hv[10];
        const ulonglong2* hp = (const ulonglong2*)hdup[par];
#pragma unroll
        for (int jj = 0; jj < 10; jj++) hv[jj] = hp[jj];

        unsigned long long aif[4], ago[4];
        aif[0] = pk2(pc.x, pc.y); ago[0] = pk2(pc.z, pc.w);
        aif[1] = aif[2] = aif[3] = 0ull;
        ago[1] = ago[2] = ago[3] = 0ull;
#pragma unroll
        for (int j = 0; j < 20; j++) {
            unsigned long long h2 = (j & 1) ? hv[j >> 1].y : hv[j >> 1].x;
            ffma2(aif[j & 3], h2, wif[j]);
            ffma2(ago[j & 3], h2, wgo[j]);
        }
        fadd2(aif[0], aif[1]); fadd2(aif[2], aif[3]); fadd2(aif[0], aif[2]);
        fadd2(ago[0], ago[1]); fadd2(ago[2], ago[3]); fadd2(ago[0], ago[2]);

        float zi, zf, zg, zo;
        upk2(zi, zf, aif[0]);
        upk2(zg, zo, ago[0]);

        float si = fmaf(tanh_ap(0.5f * zi), 0.5f, 0.5f);
        float sf = fmaf(tanh_ap(0.5f * zf), 0.5f, 0.5f);
        float so = fmaf(tanh_ap(0.5f * zo), 0.5f, 0.5f);
        float tg = tanh_ap(zg);
        c = fmaf(sf, c, si * tg);
        float h = so * tanh_ap(c);

        *(float2*)&hdup[par ^ 1][2 * q] = make_float2(h, h);
        if (q < 20) {
            int s = dir ? (S - 1 - it) : it;
            hout[((size_t)s * 32 + b) * 20 + q] = h;
        }
        __syncwarp();

        if (q < 20) cp_async16(s2u(&slots[it & 3][qc * 4]), rowptr(it + 4));
        cp_commit();
        par ^= 1;
    }
    cp_wait<0>();
}

// ---------------------------------------------------------------------------
// Kernel 3: emission, only the L=8 needed diagonals.
// ---------------------------------------------------------------------------
__global__ __launch_bounds__(256) void k3_emis(
    const float* __restrict__ W1, const float* __restrict__ b1,
    const float* __restrict__ W2, const float* __restrict__ b2,
    float* __restrict__ out)
{
    __shared__ float W1s[40 * 20];
    __shared__ float b1s[20];
    __shared__ float W2s[20 * 52];
    __shared__ float b2s[52];
    const int tid = threadIdx.x;
    const int t = blockIdx.x;

    for (int i = tid; i < 800; i += 256) W1s[i] = W1[i];
    if (tid < 20) b1s[tid] = b1[tid];
    for (int i = tid; i < 20 * 52; i += 256) {
        int qq = i / 52, k = i % 52;
        W2s[i] = (k < 50) ? W2[qq * 50 + k] : 0.f;
    }
    if (tid < 52) b2s[tid] = (tid < 50) ? b2[tid] : 0.f;
    __syncthreads();

    const int l = tid >> 5, b = tid & 31;
    const int s0 = t - 7 + l;
    float* op = out + ((((size_t)l * 256 + t) * 32 + b) * 50);

    if (s0 < 0) {
#pragma unroll
        for (int k = 0; k < 50; k += 2) *(float2*)&op[k] = make_float2(NEGV, NEGV);
        return;
    }

    float cat[40];
    const float* hfe = g_hf + ((size_t)(t + 2) * 32 + b) * 20;
    const float* hfs = g_hf + ((size_t)(s0 + 1) * 32 + b) * 20;
    const float* hbs = g_hb + ((size_t)s0 * 32 + b) * 20;
    const float* hbe = g_hb + ((size_t)(t + 1) * 32 + b) * 20;
#pragma unroll
    for (int j = 0; j < 20; j += 4) {
        float4 a  = *(const float4*)(hfe + j), c4 = *(const float4*)(hfs + j);
        cat[j]     = a.x - c4.x; cat[j + 1] = a.y - c4.y;
        cat[j + 2] = a.z - c4.z; cat[j + 3] = a.w - c4.w;
        float4 d  = *(const float4*)(hbs + j), e4 = *(const float4*)(hbe + j);
        cat[20 + j]     = d.x - e4.x; cat[20 + j + 1] = d.y - e4.y;
        cat[20 + j + 2] = d.z - e4.z; cat[20 + j + 3] = d.w - e4.w;
    }

    float hid[20];
#pragma unroll
    for (int v = 0; v < 20; v++) hid[v] = b1s[v];
#pragma unroll
    for (int j = 0; j < 40; j++) {
        float cj = cat[j];
#pragma unroll
        for (int v = 0; v < 20; v += 4) {
            float4 wv = *(const float4*)&W1s[j * 20 + v];
            hid[v]     = fmaf(cj, wv.x, hid[v]);
            hid[v + 1] = fmaf(cj, wv.y, hid[v + 1]);
            hid[v + 2] = fmaf(cj, wv.z, hid[v + 2]);
            hid[v + 3] = fmaf(cj, wv.w, hid[v + 3]);
        }
    }
#pragma unroll
    for (int v = 0; v < 20; v++) hid[v] = tanh_ap(hid[v]);

#pragma unroll
    for (int half = 0; half < 2; half++) {
        const int ko = half * 26;
        float o[26];
#pragma unroll
        for (int v = 0; v < 26; v++) o[v] = b2s[ko + v];
#pragma unroll
        for (int qq = 0; qq < 20; qq++) {
            float hq = hid[qq];
            const float* wrow = &W2s[qq * 52 + ko];
#pragma unroll
            for (int v = 0; v < 26; v += 2) {
                float2 wv = *(const float2*)&wrow[v];
                o[v]     = fmaf(hq, wv.x, o[v]);
                o[v + 1] = fmaf(hq, wv.y, o[v + 1]);
            }
        }
        const int lim = (half == 0) ? 26 : 24;
#pragma unroll
        for (int k = 0; k < 26; k += 2) {
            if (k < lim) *(float2*)&op[ko + k] = make_float2(o[k], o[k + 1]);
        }
    }
}

// ---------------------------------------------------------------------------
extern "C" void kernel_launch(void* const* d_in, const int* in_sizes, int n_in,
                              void* d_out, int out_size)
{
    const int*   x   = (const int*)d_in[0];
    const float* emb = (const float*)d_in[1];
    const float* Wif = (const float*)d_in[2];
    const float* Whf = (const float*)d_in[3];
    const float* bf  = (const float*)d_in[4];
    const float* Wib = (const float*)d_in[5];
    const float* Whb = (const float*)d_in[6];
    const float* bb  = (const float*)d_in[7];
    const float* W1  = (const float*)d_in[8];
    const float* b1  = (const float*)d_in[9];
    const float* W2  = (const float*)d_in[10];
    const float* b2  = (const float*)d_in[11];
    float* out = (float*)d_out;

    k1_embed_gemm<<<129, 512>>>(x, emb, Wif, bf, Wib, bb);
    k2_lstm<<<64, 32>>>(Whf, Whb);
    k3_emis<<<256, 256>>>(W1, b1, W2, b2, out);
}

// round 5
// speedup vs baseline: 1.6267x; 1.1373x over previous
#include <cuda_runtime.h>
#include <cstdint>
#include <cstddef>

#define NEGV -1e30f

constexpr int Bb = 32, Tt = 256, S = 258, Q = 20;

// h outputs for k3
__device__ float g_hf[S * Bb * Q];
__device__ float g_hb[S * Bb * Q];

// ---- helpers --------------------------------------------------------------
__device__ __forceinline__ unsigned long long pk2(float lo, float hi) {
    unsigned long long r;
    asm("mov.b64 %0, {%1, %2};" : "=l"(r) : "f"(lo), "f"(hi));
    return r;
}
__device__ __forceinline__ void upk2(float& lo, float& hi, unsigned long long v) {
    asm("mov.b64 {%0, %1}, %2;" : "=f"(lo), "=f"(hi) : "l"(v));
}
__device__ __forceinline__ void ffma2(unsigned long long& d, unsigned long long a,
                                      unsigned long long b) {
    asm("fma.rn.f32x2 %0, %1, %2, %0;" : "+l"(d) : "l"(a), "l"(b));
}
__device__ __forceinline__ float tanh_ap(float x) {
    float y;
    asm("tanh.approx.f32 %0, %1;" : "=f"(y) : "f"(x));
    return y;
}
__device__ __forceinline__ uint32_t s2u(const void* p) {
    uint32_t a;
    asm("{ .reg .u64 t; cvta.to.shared.u64 t, %1; cvt.u32.u64 %0, t; }"
        : "=r"(a) : "l"(p));
    return a;
}
__device__ __forceinline__ void cp_async16(uint32_t dst, const void* src) {
    asm volatile("cp.async.ca.shared.global [%0], [%1], 16;" :: "r"(dst), "l"(src));
}
__device__ __forceinline__ void cp_commit() {
    asm volatile("cp.async.commit_group;" ::: "memory");
}
template <int N> __device__ __forceinline__ void cp_wait() {
    asm volatile("cp.async.wait_group %0;" :: "n"(N) : "memory");
}

// ---- fused kernel shared layout ------------------------------------------
struct __align__(16) SML {
    float pre[S][80];        // pre-gates, permuted [it][q*4+gate]   82560 B
    float W[128][80];        // W_ih (source layout [k][gt*20+q])    40960 B
    float A[2][32][128];     // embedding chunk ring                 32768 B
    int   tok[260];          //                                       1040 B
    float bias[80];          //                                        320 B
    float hsh[24];           // current h (20 used)                     96 B
};                           // total ~157,744 B

// ---------------------------------------------------------------------------
// One LSTM step (consumer warp). Lane qc owns cell qc.
// ---------------------------------------------------------------------------
__device__ __forceinline__ void lstm_step(
    SML& sm, const unsigned long long (&wpk)[4][10], float& cst,
    int it, int dir, int b, int qc, bool active, float* __restrict__ hout)
{
    float4 pc = *(const float4*)&sm.pre[it][qc * 4];   // (i,f,g,o) pre-gates

    const ulonglong2* hp = (const ulonglong2*)sm.hsh;
    ulonglong2 h0 = hp[0], h1 = hp[1], h2 = hp[2], h3 = hp[3], h4 = hp[4];
    unsigned long long pr[10] = {h0.x, h0.y, h1.x, h1.y, h2.x,
                                 h2.y, h3.x, h3.y, h4.x, h4.y};

    unsigned long long a0 = 0ull, a1 = 0ull, a2 = 0ull, a3 = 0ull;
#pragma unroll
    for (int jp = 0; jp < 10; jp++) {
        ffma2(a0, pr[jp], wpk[0][jp]);
        ffma2(a1, pr[jp], wpk[1][jp]);
        ffma2(a2, pr[jp], wpk[2][jp]);
        ffma2(a3, pr[jp], wpk[3][jp]);
    }
    float lo, hi;
    upk2(lo, hi, a0); float zi = pc.x + lo + hi;
    upk2(lo, hi, a1); float zf = pc.y + lo + hi;
    upk2(lo, hi, a2); float zg = pc.z + lo + hi;
    upk2(lo, hi, a3); float zo = pc.w + lo + hi;

    float si = fmaf(tanh_ap(0.5f * zi), 0.5f, 0.5f);
    float sf = fmaf(tanh_ap(0.5f * zf), 0.5f, 0.5f);
    float so = fmaf(tanh_ap(0.5f * zo), 0.5f, 0.5f);
    float tg = tanh_ap(zg);
    cst = fmaf(sf, cst, si * tg);
    float h = so * tanh_ap(cst);

    if (active) {
        sm.hsh[qc] = h;
        int s = dir ? (S - 1 - it) : it;
        hout[((size_t)s * 32 + b) * 20 + qc] = h;
    }
    __syncwarp();
}

// ---------------------------------------------------------------------------
// Fused kernel: one block per (dir, batch), 288 threads.
//  - warps 0..7 (256 thr): producers — per-chunk GEMM [32,128]x[128,80] into
//    sm.pre (permuted), embeddings streamed via cp.async ring.
//  - warp 8 (32 thr): consumer — LSTM recurrence over sm.pre, one chunk behind.
// __syncthreads() per chunk keeps the producer exactly one chunk ahead.
// ---------------------------------------------------------------------------
__global__ __launch_bounds__(288, 1) void k12_fused(
    const int* __restrict__ x, const float* __restrict__ emb,
    const float* __restrict__ Wif, const float* __restrict__ bfv,
    const float* __restrict__ Wib, const float* __restrict__ bbv,
    const float* __restrict__ Whf, const float* __restrict__ Whb)
{
    extern __shared__ char raw[];
    SML& sm = *(SML*)raw;
    const int tid = threadIdx.x;
    const int lane = tid & 31;
    const int dir = blockIdx.x >> 5;
    const int b = blockIdx.x & 31;
    const float* Wih = dir ? Wib : Wif;
    const float* bia = dir ? bbv : bfv;
    const float* Whh = dir ? Whb : Whf;
    float* hout      = dir ? g_hb : g_hf;
    const bool isProd = (tid < 256);

    // tokens + bias into smem
    if (tid < 256) sm.tok[tid + 1] = x[b * Tt + tid];
    if (tid == 256) { sm.tok[0] = 2; sm.tok[S - 1] = 3; }
    if (tid < 80) sm.bias[tid] = bia[tid];

    // consumer: load recurrent weights into registers as (k-even,k-odd) pairs
    unsigned long long wpk[4][10];
    float creg = 0.f;
    const int qc = lane < 20 ? lane : 19;
    if (!isProd) {
#pragma unroll
        for (int gt = 0; gt < 4; gt++)
#pragma unroll
            for (int jp = 0; jp < 10; jp++)
                wpk[gt][jp] = pk2(Whh[(2 * jp) * 80 + gt * 20 + qc],
                                  Whh[(2 * jp + 1) * 80 + gt * 20 + qc]);
        if (lane < 24) sm.hsh[lane] = 0.f;
    }
    __syncthreads();   // tokens/bias/hsh visible

    // prologue cp.async: W_ih (group 0), A chunk 0 (group 1)
    if (isProd) {
#pragma unroll
        for (int i = 0; i < 10; i++) {
            int f = tid + i * 256;                 // 0..2559 float4s
            cp_async16(s2u((char*)sm.W + f * 16), Wih + f * 4);
        }
        cp_commit();
#pragma unroll
        for (int i = 0; i < 4; i++) {
            int f = tid + i * 256;                 // 1024 float4s
            int rr = f >> 5, k4 = f & 31;
            int s = dir ? (S - 1 - rr) : rr;
            cp_async16(s2u(&sm.A[0][rr][k4 * 4]),
                       emb + (size_t)sm.tok[s] * 128 + k4 * 4);
        }
        cp_commit();
    }

    const int r = tid >> 3;          // producer: row in chunk (0..31)
    const int c0 = (tid & 7) * 10;   // producer: 10 source cols

    for (int ch = 0; ch < 9; ch++) {
        if (isProd) {
            // prefetch A for chunk ch+1
            if (ch < 8) {
#pragma unroll
                for (int i = 0; i < 4; i++) {
                    int f = tid + i * 256;
                    int rr = f >> 5, k4 = f & 31;
                    int itn = (ch + 1) * 32 + rr;
                    if (itn < S) {
                        int s = dir ? (S - 1 - itn) : itn;
                        cp_async16(s2u(&sm.A[(ch + 1) & 1][rr][k4 * 4]),
                                   emb + (size_t)sm.tok[s] * 128 + k4 * 4);
                    }
                }
            }
            cp_commit();
            cp_wait<1>();      // chunk ch's A (and W) complete

            int it = ch * 32 + r;
            if (it < S) {
                const float* Arow = sm.A[ch & 1][r];
                unsigned long long acc[5] = {0ull, 0ull, 0ull, 0ull, 0ull};
#pragma unroll 4
                for (int k = 0; k < 128; k++) {
                    float a = Arow[k];
                    unsigned long long ap = pk2(a, a);
#pragma unroll
                    for (int j = 0; j < 5; j++)
                        ffma2(acc[j], ap,
                              *(const unsigned long long*)&sm.W[k][c0 + 2 * j]);
                }
#pragma unroll
                for (int j = 0; j < 5; j++) {
                    float lo, hi;
                    upk2(lo, hi, acc[j]);
                    int cA = c0 + 2 * j, cB = cA + 1;
                    sm.pre[it][(cA % 20) * 4 + cA / 20] = lo + sm.bias[cA];
                    sm.pre[it][(cB % 20) * 4 + cB / 20] = hi + sm.bias[cB];
                }
            }
        } else if (ch > 0) {
            // consume chunk ch-1 (32 steps)
            int base = (ch - 1) * 32;
            for (int i = 0; i < 32; i++)
                lstm_step(sm, wpk, creg, base + i, dir, b, qc, lane < 20, hout);
        }
        __syncthreads();
    }

    // consumer epilogue: chunk 8 = steps 256, 257
    if (!isProd) {
        lstm_step(sm, wpk, creg, 256, dir, b, qc, lane < 20, hout);
        lstm_step(sm, wpk, creg, 257, dir, b, qc, lane < 20, hout);
    }
}

// ---------------------------------------------------------------------------
// Kernel 3: emission, only the L=8 needed diagonals.
// ---------------------------------------------------------------------------
__global__ __launch_bounds__(256) void k3_emis(
    const float* __restrict__ W1, const float* __restrict__ b1,
    const float* __restrict__ W2, const float* __restrict__ b2,
    float* __restrict__ out)
{
    __shared__ float W1s[40 * 20];
    __shared__ float b1s[20];
    __shared__ float W2s[20 * 52];
    __shared__ float b2s[52];
    const int tid = threadIdx.x;
    const int t = blockIdx.x;

    for (int i = tid; i < 800; i += 256) W1s[i] = W1[i];
    if (tid < 20) b1s[tid] = b1[tid];
    for (int i = tid; i < 20 * 52; i += 256) {
        int qq = i / 52, k = i % 52;
        W2s[i] = (k < 50) ? W2[qq * 50 + k] : 0.f;
    }
    if (tid < 52) b2s[tid] = (tid < 50) ? b2[tid] : 0.f;
    __syncthreads();

    const int l = tid >> 5, b = tid & 31;
    const int s0 = t - 7 + l;
    float* op = out + ((((size_t)l * 256 + t) * 32 + b) * 50);

    if (s0 < 0) {
#pragma unroll
        for (int k = 0; k < 50; k += 2) *(float2*)&op[k] = make_float2(NEGV, NEGV);
        return;
    }

    float cat[40];
    const float* hfe = g_hf + ((size_t)(t + 2) * 32 + b) * 20;
    const float* hfs = g_hf + ((size_t)(s0 + 1) * 32 + b) * 20;
    const float* hbs = g_hb + ((size_t)s0 * 32 + b) * 20;
    const float* hbe = g_hb + ((size_t)(t + 1) * 32 + b) * 20;
#pragma unroll
    for (int j = 0; j < 20; j += 4) {
        float4 a  = *(const float4*)(hfe + j), c4 = *(const float4*)(hfs + j);
        cat[j]     = a.x - c4.x; cat[j + 1] = a.y - c4.y;
        cat[j + 2] = a.z - c4.z; cat[j + 3] = a.w - c4.w;
        float4 d  = *(const float4*)(hbs + j), e4 = *(const float4*)(hbe + j);
        cat[20 + j]     = d.x - e4.x; cat[20 + j + 1] = d.y - e4.y;
        cat[20 + j + 2] = d.z - e4.z; cat[20 + j + 3] = d.w - e4.w;
    }

    float hid[20];
#pragma unroll
    for (int v = 0; v < 20; v++) hid[v] = b1s[v];
#pragma unroll
    for (int j = 0; j < 40; j++) {
        float cj = cat[j];
#pragma unroll
        for (int v = 0; v < 20; v += 4) {
            float4 wv = *(const float4*)&W1s[j * 20 + v];
            hid[v]     = fmaf(cj, wv.x, hid[v]);
            hid[v + 1] = fmaf(cj, wv.y, hid[v + 1]);
            hid[v + 2] = fmaf(cj, wv.z, hid[v + 2]);
            hid[v + 3] = fmaf(cj, wv.w, hid[v + 3]);
        }
    }
#pragma unroll
    for (int v = 0; v < 20; v++) hid[v] = tanh_ap(hid[v]);

#pragma unroll
    for (int half = 0; half < 2; half++) {
        const int ko = half * 26;
        float o[26];
#pragma unroll
        for (int v = 0; v < 26; v++) o[v] = b2s[ko + v];
#pragma unroll
        for (int qq = 0; qq < 20; qq++) {
            float hq = hid[qq];
            const float* wrow = &W2s[qq * 52 + ko];
#pragma unroll
            for (int v = 0; v < 26; v += 2) {
                float2 wv = *(const float2*)&wrow[v];
                o[v]     = fmaf(hq, wv.x, o[v]);
                o[v + 1] = fmaf(hq, wv.y, o[v + 1]);
            }
        }
        const int lim = (half == 0) ? 26 : 24;
#pragma unroll
        for (int k = 0; k < 26; k += 2) {
            if (k < lim) *(float2*)&op[ko + k] = make_float2(o[k], o[k + 1]);
        }
    }
}

// ---------------------------------------------------------------------------
extern "C" void kernel_launch(void* const* d_in, const int* in_sizes, int n_in,
                              void* d_out, int out_size)
{
    const int*   x   = (const int*)d_in[0];
    const float* emb = (const float*)d_in[1];
    const float* Wif = (const float*)d_in[2];
    const float* Whf = (const float*)d_in[3];
    const float* bf  = (const float*)d_in[4];
    const float* Wib = (const float*)d_in[5];
    const float* Whb = (const float*)d_in[6];
    const float* bb  = (const float*)d_in[7];
    const float* W1  = (const float*)d_in[8];
    const float* b1  = (const float*)d_in[9];
    const float* W2  = (const float*)d_in[10];
    const float* b2  = (const float*)d_in[11];
    float* out = (float*)d_out;

    cudaFuncSetAttribute(k12_fused, cudaFuncAttributeMaxDynamicSharedMemorySize,
                         (int)sizeof(SML));
    k12_fused<<<64, 288, sizeof(SML)>>>(x, emb, Wif, bf, Wib, bb, Whf, Whb);
    k3_emis<<<256, 256>>>(W1, b1, W2, b2, out);
}

// round 6
// speedup vs baseline: 1.6673x; 1.0250x over previous
#include <cuda_runtime.h>
#include <cstdint>
#include <cstddef>

#define NEGV -1e30f

constexpr int Bb = 32, Tt = 256, S = 258, Q = 20;

// h outputs for k3
__device__ float g_hf[S * Bb * Q];
__device__ float g_hb[S * Bb * Q];

typedef unsigned long long ull;

// ---- helpers --------------------------------------------------------------
__device__ __forceinline__ ull pk2(float lo, float hi) {
    ull r;
    asm("mov.b64 %0, {%1, %2};" : "=l"(r) : "f"(lo), "f"(hi));
    return r;
}
__device__ __forceinline__ void upk2(float& lo, float& hi, ull v) {
    asm("mov.b64 {%0, %1}, %2;" : "=f"(lo), "=f"(hi) : "l"(v));
}
__device__ __forceinline__ void ffma2(ull& d, ull a, ull b) {
    asm("fma.rn.f32x2 %0, %1, %2, %0;" : "+l"(d) : "l"(a), "l"(b));
}
__device__ __forceinline__ void fadd2(ull& d, ull a) {
    asm("add.rn.f32x2 %0, %0, %1;" : "+l"(d) : "l"(a));
}
__device__ __forceinline__ float tanh_ap(float x) {
    float y;
    asm("tanh.approx.f32 %0, %1;" : "=f"(y) : "f"(x));
    return y;
}
__device__ __forceinline__ uint32_t s2u(const void* p) {
    uint32_t a;
    asm("{ .reg .u64 t; cvta.to.shared.u64 t, %1; cvt.u32.u64 %0, t; }"
        : "=r"(a) : "l"(p));
    return a;
}
__device__ __forceinline__ void cp_async16(uint32_t dst, const void* src) {
    asm volatile("cp.async.ca.shared.global [%0], [%1], 16;" :: "r"(dst), "l"(src));
}
__device__ __forceinline__ void cp_commit() {
    asm volatile("cp.async.commit_group;" ::: "memory");
}
template <int N> __device__ __forceinline__ void cp_wait() {
    asm volatile("cp.async.wait_group %0;" :: "n"(N) : "memory");
}
#define CREW_BAR(id) asm volatile("bar.sync %0, %1;" :: "r"(id), "r"(96) : "memory")

// ---- fused kernel shared layout ------------------------------------------
struct __align__(16) SML {
    float pre[S][80];        // pre-gates, natural [it][gt*20+q]     82560 B
    float W[128][80];        // W_ih [k][gt*20+q]                    40960 B
    float A[2][32][128];     // embedding chunk ring                 32768 B
    int   tok[260];
    float bias[80];
    float act[80];           // activated gates [q*4 + gt]
    float hsh[32];           // current h (20 used)
};

// ---------------------------------------------------------------------------
// Fused kernel: one block per (dir, batch), 352 threads.
//  - warps 0..7 (256 thr): producers — chunked GEMM [32,128]x[128,80] into
//    sm.pre, embeddings streamed via cp.async ring, one chunk ahead.
//  - warps 8..10 (96 thr): recurrence crew — lane = one gate (gt*20+q).
//    Each step: 10 FFMA2 gate dot + MUFU activation -> named bar ->
//    warp 10 lanes 0..19 do cell/h update -> named bar.
// ---------------------------------------------------------------------------
__global__ __launch_bounds__(352, 1) void k12_fused(
    const int* __restrict__ x, const float* __restrict__ emb,
    const float* __restrict__ Wif, const float* __restrict__ bfv,
    const float* __restrict__ Wib, const float* __restrict__ bbv,
    const float* __restrict__ Whf, const float* __restrict__ Whb)
{
    extern __shared__ char raw[];
    SML& sm = *(SML*)raw;
    const int tid = threadIdx.x;
    const int dir = blockIdx.x >> 5;
    const int b = blockIdx.x & 31;
    const float* Wih = dir ? Wib : Wif;
    const float* bia = dir ? bbv : bfv;
    const float* Whh = dir ? Whb : Whf;
    float* hout      = dir ? g_hb : g_hf;
    const bool isProd = (tid < 256);

    if (tid < 256) sm.tok[tid + 1] = x[b * Tt + tid];
    if (tid == 256) { sm.tok[0] = 2; sm.tok[S - 1] = 3; }
    if (tid < 80) sm.bias[tid] = bia[tid];

    // ---- crew setup ----
    const int ct = tid - 256;                 // 0..95 for crew
    const int lane = tid & 31;
    const bool gact = (ct >= 0) && (ct < 80);
    const int gcl = gact ? ct : 79;           // clamped gate index
    const int ggt = gcl / 20, gq = gcl % 20;
    const float szc = (ggt == 2) ? 1.f : 0.5f;
    const float aac = (ggt == 2) ? 1.f : 0.5f;
    const float bbc = (ggt == 2) ? 0.f : 0.5f;
    const bool isCrew = (tid >= 256);
    const bool epi = isCrew && (ct >= 64) && (lane < 20);   // warp 10 lanes 0..19
    ull wk[10];
    float creg = 0.f;
    if (isCrew) {
#pragma unroll
        for (int j = 0; j < 10; j++)
            wk[j] = pk2(Whh[(2 * j) * 80 + gcl], Whh[(2 * j + 1) * 80 + gcl]);
        if (ct < 32) sm.hsh[ct] = 0.f;
    }
    __syncthreads();

    // ---- producer prologue: W_ih (group), A chunk 0 (group) ----
    if (isProd) {
#pragma unroll
        for (int i = 0; i < 10; i++) {
            int f = tid + i * 256;             // 2560 float4s
            cp_async16(s2u((char*)sm.W + f * 16), Wih + f * 4);
        }
        cp_commit();
#pragma unroll
        for (int i = 0; i < 4; i++) {
            int f = tid + i * 256;             // 1024 float4s
            int rr = f >> 5, k4 = f & 31;
            int s = dir ? (S - 1 - rr) : rr;
            cp_async16(s2u(&sm.A[0][rr][k4 * 4]),
                       emb + (size_t)sm.tok[s] * 128 + k4 * 4);
        }
        cp_commit();
    }

    const int r = tid >> 3;          // producer: row in chunk (0..31)
    const int c0 = (tid & 7) * 10;   // producer: 10 cols

    // one crew step
    auto crew_step = [&](int it) {
        float prez = sm.pre[it][gcl];
        const ulonglong2* hp = (const ulonglong2*)sm.hsh;
        ulonglong2 h0 = hp[0], h1 = hp[1], h2 = hp[2], h3 = hp[3], h4 = hp[4];
        ull acc0 = pk2(prez, 0.f), acc1 = 0ull;
        ffma2(acc0, h0.x, wk[0]); ffma2(acc1, h0.y, wk[1]);
        ffma2(acc0, h1.x, wk[2]); ffma2(acc1, h1.y, wk[3]);
        ffma2(acc0, h2.x, wk[4]); ffma2(acc1, h2.y, wk[5]);
        ffma2(acc0, h3.x, wk[6]); ffma2(acc1, h3.y, wk[7]);
        ffma2(acc0, h4.x, wk[8]); ffma2(acc1, h4.y, wk[9]);
        fadd2(acc0, acc1);
        float lo, hi;
        upk2(lo, hi, acc0);
        float z = lo + hi;
        float av = fmaf(tanh_ap(szc * z), aac, bbc);
        if (gact) sm.act[gq * 4 + ggt] = av;
        CREW_BAR(1);
        if (epi) {
            float4 ga = *(const float4*)&sm.act[lane * 4];   // i,f,g,o
            creg = fmaf(ga.y, creg, ga.x * ga.z);
            float h = ga.w * tanh_ap(creg);
            sm.hsh[lane] = h;
            int s = dir ? (S - 1 - it) : it;
            hout[((size_t)s * 32 + b) * 20 + lane] = h;
        }
        CREW_BAR(2);
    };

    for (int ch = 0; ch < 9; ch++) {
        if (isProd) {
            if (ch < 8) {
#pragma unroll
                for (int i = 0; i < 4; i++) {
                    int f = tid + i * 256;
                    int rr = f >> 5, k4 = f & 31;
                    int itn = (ch + 1) * 32 + rr;
                    if (itn < S) {
                        int s = dir ? (S - 1 - itn) : itn;
                        cp_async16(s2u(&sm.A[(ch + 1) & 1][rr][k4 * 4]),
                                   emb + (size_t)sm.tok[s] * 128 + k4 * 4);
                    }
                }
            }
            cp_commit();
            cp_wait<1>();

            int it = ch * 32 + r;
            if (it < S) {
                const float* Arow = sm.A[ch & 1][r];
                ull acc[5] = {0ull, 0ull, 0ull, 0ull, 0ull};
#pragma unroll 4
                for (int k = 0; k < 128; k++) {
                    float a = Arow[k];
                    ull ap = pk2(a, a);
#pragma unroll
                    for (int j = 0; j < 5; j++)
                        ffma2(acc[j], ap, *(const ull*)&sm.W[k][c0 + 2 * j]);
                }
#pragma unroll
                for (int j = 0; j < 5; j++) {
                    float lo, hi;
                    upk2(lo, hi, acc[j]);
                    float2 v;
                    v.x = lo + sm.bias[c0 + 2 * j];
                    v.y = hi + sm.bias[c0 + 2 * j + 1];
                    *(float2*)&sm.pre[it][c0 + 2 * j] = v;
                }
            }
        } else if (ch > 0) {
            int base = (ch - 1) * 32;
            for (int i = 0; i < 32; i++) crew_step(base + i);
        }
        __syncthreads();
    }

    if (isCrew) { crew_step(256); crew_step(257); }
}

// ---------------------------------------------------------------------------
// Kernel 3: emission, only the L=8 needed diagonals. FFMA2-packed MLP.
// ---------------------------------------------------------------------------
__global__ __launch_bounds__(256) void k3_emis(
    const float* __restrict__ W1, const float* __restrict__ b1,
    const float* __restrict__ W2, const float* __restrict__ b2,
    float* __restrict__ out)
{
    __shared__ __align__(16) float W1s[40][20];   // rows 80B = 5x16 aligned
    __shared__ float b1s[20];
    __shared__ __align__(16) float W2s[20][56];   // rows 224B = 14x16 aligned
    __shared__ float b2s[56];
    const int tid = threadIdx.x;
    const int t = blockIdx.x;

    for (int i = tid; i < 800; i += 256) W1s[i / 20][i % 20] = W1[i];
    if (tid < 20) b1s[tid] = b1[tid];
    for (int i = tid; i < 20 * 56; i += 256) {
        int qq = i / 56, k = i % 56;
        W2s[qq][k] = (k < 50) ? W2[qq * 50 + k] : 0.f;
    }
    if (tid < 56) b2s[tid] = (tid < 50) ? b2[tid] : 0.f;
    __syncthreads();

    const int l = tid >> 5, b = tid & 31;
    const int s0 = t - 7 + l;
    float* op = out + ((((size_t)l * 256 + t) * 32 + b) * 50);

    if (s0 < 0) {
#pragma unroll
        for (int k = 0; k < 50; k += 2) *(float2*)&op[k] = make_float2(NEGV, NEGV);
        return;
    }

    float cat[40];
    const float* hfe = g_hf + ((size_t)(t + 2) * 32 + b) * 20;
    const float* hfs = g_hf + ((size_t)(s0 + 1) * 32 + b) * 20;
    const float* hbs = g_hb + ((size_t)s0 * 32 + b) * 20;
    const float* hbe = g_hb + ((size_t)(t + 1) * 32 + b) * 20;
#pragma unroll
    for (int j = 0; j < 20; j += 4) {
        float4 a  = *(const float4*)(hfe + j), c4 = *(const float4*)(hfs + j);
        cat[j]     = a.x - c4.x; cat[j + 1] = a.y - c4.y;
        cat[j + 2] = a.z - c4.z; cat[j + 3] = a.w - c4.w;
        float4 d  = *(const float4*)(hbs + j), e4 = *(const float4*)(hbe + j);
        cat[20 + j]     = d.x - e4.x; cat[20 + j + 1] = d.y - e4.y;
        cat[20 + j + 2] = d.z - e4.z; cat[20 + j + 3] = d.w - e4.w;
    }

    // layer 1: 10 packed accumulators
    ull hacc[10];
#pragma unroll
    for (int v = 0; v < 10; v++) hacc[v] = pk2(b1s[2 * v], b1s[2 * v + 1]);
#pragma unroll
    for (int j = 0; j < 40; j++) {
        ull cj2 = pk2(cat[j], cat[j]);
        const ull* wr = (const ull*)W1s[j];
#pragma unroll
        for (int v = 0; v < 10; v++) ffma2(hacc[v], cj2, wr[v]);
    }
    float hid[20];
#pragma unroll
    for (int v = 0; v < 10; v++) upk2(hid[2 * v], hid[2 * v + 1], hacc[v]);
#pragma unroll
    for (int v = 0; v < 20; v++) hid[v] = tanh_ap(hid[v]);

    // layer 2: two halves of 28 cols (14 packed accumulators each)
#pragma unroll
    for (int half = 0; half < 2; half++) {
        const int kb = half * 28;
        ull oacc[14];
#pragma unroll
        for (int v = 0; v < 14; v++)
            oacc[v] = pk2(b2s[kb + 2 * v], b2s[kb + 2 * v + 1]);
#pragma unroll
        for (int qq = 0; qq < 20; qq++) {
            ull h2 = pk2(hid[qq], hid[qq]);
            const ull* w2r = (const ull*)&W2s[qq][kb];
#pragma unroll
            for (int v = 0; v < 14; v++) ffma2(oacc[v], h2, w2r[v]);
        }
#pragma unroll
        for (int v = 0; v < 14; v++) {
            if (kb + 2 * v < 50) {
                float lo, hi;
                upk2(lo, hi, oacc[v]);
                *(float2*)&op[kb + 2 * v] = make_float2(lo, hi);
            }
        }
    }
}

// ---------------------------------------------------------------------------
extern "C" void kernel_launch(void* const* d_in, const int* in_sizes, int n_in,
                              void* d_out, int out_size)
{
    const int*   x   = (const int*)d_in[0];
    const float* emb = (const float*)d_in[1];
    const float* Wif = (const float*)d_in[2];
    const float* Whf = (const float*)d_in[3];
    const float* bf  = (const float*)d_in[4];
    const float* Wib = (const float*)d_in[5];
    const float* Whb = (const float*)d_in[6];
    const float* bb  = (const float*)d_in[7];
    const float* W1  = (const float*)d_in[8];
    const float* b1  = (const float*)d_in[9];
    const float* W2  = (const float*)d_in[10];
    const float* b2  = (const float*)d_in[11];
    float* out = (float*)d_out;

    cudaFuncSetAttribute(k12_fused, cudaFuncAttributeMaxDynamicSharedMemorySize,
                         (int)sizeof(SML));
    k12_fused<<<64, 352, sizeof(SML)>>>(x, emb, Wif, bf, Wib, bb, Whf, Whb);
    k3_emis<<<256, 256>>>(W1, b1, W2, b2, out);
}